// round 9
// baseline (speedup 1.0000x reference)
#include <cuda_runtime.h>
#include <cstdint>
#include <cstddef>

#define T_LEN 16384
#define L_LAB 1024
#define LOG2E 1.4426950408889634f
#define LN2_D 0.6931471805599453
#define NBLK  128
#define TPB   256

// ---- persistent state (scratch; no allocations allowed) ----
__device__ unsigned long long g_pub[2][L_LAB];  // {tag<<32 | float_bits}
__device__ unsigned int      g_arr[NBLK];       // arrive[b] = latest step published by block b
__device__ double g_csum;
__device__ double g_gold;

static __device__ __forceinline__ float ex2f(float x) {
    float r; asm("ex2.approx.ftz.f32 %0, %1;" : "=f"(r) : "f"(x)); return r;
}
static __device__ __forceinline__ float lg2f_(float x) {
    float r; asm("lg2.approx.f32 %0, %1;" : "=f"(r) : "f"(x)); return r;
}
static __device__ __forceinline__ unsigned long long ld_pub(const unsigned long long* p) {
    unsigned long long v;
    asm volatile("ld.relaxed.gpu.global.b64 %0, [%1];" : "=l"(v) : "l"(p));
    return v;
}
static __device__ __forceinline__ void st_pub(unsigned long long* p, unsigned long long v) {
    asm volatile("st.relaxed.gpu.global.b64 [%0], %1;" :: "l"(p), "l"(v));
}
static __device__ __forceinline__ unsigned ld_arr(const unsigned* p) {
    unsigned v;
    asm volatile("ld.relaxed.gpu.global.b32 %0, [%1];" : "=r"(v) : "l"(p));
    return v;
}
static __device__ __forceinline__ void st_arr(unsigned* p, unsigned v) {
    asm volatile("st.relaxed.gpu.global.b32 [%0], %1;" :: "l"(p), "r"(v));
}

__global__ void crf_reset() {
    int i = blockIdx.x * blockDim.x + threadIdx.x;
    if (i < 2 * L_LAB) ((unsigned long long*)g_pub)[i] = 0ull;
    if (i < NBLK) g_arr[i] = 0u;
}

// Blocks 0..127: forward recurrence, 8 label-rows per block, one row per warp,
// W row resident in 32 registers/thread. Block 128: gold-path score.
__global__ void __launch_bounds__(TPB, 1) crf_main(const float* __restrict__ pred,
                                                   const int*   __restrict__ ref,
                                                   const float* __restrict__ trans)
{
    if (blockIdx.x == NBLK) {
        __shared__ double red[TPB];
        int tid = threadIdx.x;
        double g = 0.0;
        for (int t = tid; t < T_LEN; t += TPB) {
            int r = __ldg(&ref[t]);
            int p = (t == 0) ? (L_LAB - 2) : __ldg(&ref[t - 1]);
            g += (double)__ldg(&pred[(size_t)t * L_LAB + r])
               + (double)__ldg(&trans[(size_t)r * L_LAB + p]);
        }
        red[tid] = g; __syncthreads();
        for (int s = TPB / 2; s > 0; s >>= 1) {
            if (tid < s) red[tid] += red[tid + s];
            __syncthreads();
        }
        if (tid == 0)
            g_gold = red[0] + (double)__ldg(&trans[(size_t)(L_LAB - 1) * L_LAB + __ldg(&ref[T_LEN - 1])]);
        return;
    }

    __shared__ __align__(16) float smA[2][L_LAB];   // double-buffered stage
    const int tid = threadIdx.x;
    const int w = tid >> 5, l = tid & 31;
    const int j = blockIdx.x * 8 + w;   // this warp's output label row

    // Load W[j,:] * log2e into 32 registers. Element i = k*128 + 4*l + m -> wr[4k+m].
    float wr[32];
    {
        const float* tr = trans + (size_t)j * L_LAB;
        #pragma unroll
        for (int k = 0; k < 8; ++k) {
            float4 v = *reinterpret_cast<const float4*>(tr + k * 128 + 4 * l);
            wr[4 * k + 0] = v.x * LOG2E; wr[4 * k + 1] = v.y * LOG2E;
            wr[4 * k + 2] = v.z * LOG2E; wr[4 * k + 3] = v.w * LOG2E;
        }
    }
    // W[j, START]: i = 1022 -> k=7, lane 31, m=2 -> reg 30
    float wstart = __shfl_sync(0xffffffffu, wr[30], 31);

    // Step 1 closed form: A''(1)[j] = (W[j,START] + pred[0,j]) * log2e
    {
        float a1 = wstart + __ldg(&pred[j]) * LOG2E;
        if (l == 0)
            st_pub(&g_pub[1][j],
                   ((unsigned long long)1u << 32) | (unsigned long long)__float_as_uint(a1));
    }
    __syncthreads();
    if (tid == 0) st_arr(&g_arr[blockIdx.x], 1u);   // block published step 1

    double csum = 0.0;
    float fnext = __ldg(&pred[(size_t)L_LAB + j]);   // feats for t=1

    for (int t = 1; t < T_LEN; ++t) {
        const int buf = t & 1;
        const unsigned tag = (unsigned)t;

        // ---- 1) wait for all 128 blocks to have published step t.
        // Threads 0..127 each spin on one 4-byte arrive word (4 hot lines
        // chip-wide instead of 64 -> ~60x less poll traffic than data-polling).
        if (tid < NBLK) {
            while (ld_arr(&g_arr[tid]) < tag) { }
        }
        __syncthreads();

        // ---- 2) single burst load of the tagged alpha vector (8 KB).
        // Tags are re-verified (arrive flags are only a hint); stale reads are
        // rare and resolve after a short re-poll.
        {
            unsigned long long* src = g_pub[buf];
            float v0, v1, v2, v3;
            unsigned pending = 0xFu;
            v0 = v1 = v2 = v3 = 0.f;
            do {
                unsigned long long e0 = 0, e1 = 0, e2 = 0, e3 = 0;
                if (pending & 1u) e0 = ld_pub(src + tid);
                if (pending & 2u) e1 = ld_pub(src + tid + 256);
                if (pending & 4u) e2 = ld_pub(src + tid + 512);
                if (pending & 8u) e3 = ld_pub(src + tid + 768);
                if ((pending & 1u) && (unsigned)(e0 >> 32) == tag) {
                    v0 = __uint_as_float((unsigned)e0); pending &= ~1u;
                }
                if ((pending & 2u) && (unsigned)(e1 >> 32) == tag) {
                    v1 = __uint_as_float((unsigned)e1); pending &= ~2u;
                }
                if ((pending & 4u) && (unsigned)(e2 >> 32) == tag) {
                    v2 = __uint_as_float((unsigned)e2); pending &= ~4u;
                }
                if ((pending & 8u) && (unsigned)(e3 >> 32) == tag) {
                    v3 = __uint_as_float((unsigned)e3); pending &= ~8u;
                }
            } while (pending);
            smA[buf][tid]       = v0;
            smA[buf][tid + 256] = v1;
            smA[buf][tid + 512] = v2;
            smA[buf][tid + 768] = v3;
        }
        __syncthreads();
        float c = smA[buf][0];           // deterministic per-step normalizer
        if (blockIdx.x == 0 && tid == 0) csum += (double)c;

        float fcur = fnext;
        if (t + 1 < T_LEN) fnext = __ldg(&pred[(size_t)(t + 1) * L_LAB + j]);

        // ---- 3) row j: s = sum_i exp2(A[i] + Wl[j,i])  (MUFU-bound, ~512 cyc) ----
        float a0 = 0.f, a1 = 0.f, a2 = 0.f, a3 = 0.f;
        #pragma unroll
        for (int k = 0; k < 8; ++k) {
            float4 v = *reinterpret_cast<const float4*>(&smA[buf][k * 128 + 4 * l]);
            a0 += ex2f(v.x + wr[4 * k + 0]);
            a1 += ex2f(v.y + wr[4 * k + 1]);
            a2 += ex2f(v.z + wr[4 * k + 2]);
            a3 += ex2f(v.w + wr[4 * k + 3]);
        }
        float s = (a0 + a1) + (a2 + a3);
        #pragma unroll
        for (int o = 16; o > 0; o >>= 1) s += __shfl_xor_sync(0xffffffffu, s, o);

        // ---- 4) publish step t+1, then signal arrival after a block barrier ----
        if (l == 0) {
            float an = lg2f_(s) - c + fcur * LOG2E;
            st_pub(&g_pub[(t + 1) & 1][j],
                   ((unsigned long long)(tag + 1u) << 32)
                   | (unsigned long long)__float_as_uint(an));
        }
        __syncthreads();   // all 8 publishes issued before arrive; also protects smA
        if (tid == 0) st_arr(&g_arr[blockIdx.x], tag + 1u);
    }

    if (blockIdx.x == 0 && tid == 0) g_csum = csum;
}

// Terminal: forward = LSE_j(A''(T)[j] + Wl[STOP,j]) + Csum (max-stabilized: the
// STOP row is uniformly -1e4, so without the max everything underflows).
__global__ void crf_final(const float* __restrict__ trans, float* __restrict__ out)
{
    __shared__ float  sm[TPB];
    __shared__ double sd[TPB];
    int tid = threadIdx.x;

    float x[4];
    float m = -3.4e38f;
    #pragma unroll
    for (int q = 0; q < 4; ++q) {
        int jj = q * TPB + tid;
        float a  = __uint_as_float((unsigned)(g_pub[T_LEN & 1][jj] & 0xffffffffull));
        float wl = __ldg(&trans[(size_t)(L_LAB - 1) * L_LAB + jj]) * LOG2E;
        x[q] = a + wl;
        m = fmaxf(m, x[q]);
    }
    sm[tid] = m; __syncthreads();
    for (int s = TPB / 2; s > 0; s >>= 1) {
        if (tid < s) sm[tid] = fmaxf(sm[tid], sm[tid + s]);
        __syncthreads();
    }
    float M = sm[0];

    double loc = 0.0;
    #pragma unroll
    for (int q = 0; q < 4; ++q) loc += (double)ex2f(x[q] - M);
    sd[tid] = loc; __syncthreads();
    for (int s = TPB / 2; s > 0; s >>= 1) {
        if (tid < s) sd[tid] += sd[tid + s];
        __syncthreads();
    }
    if (tid == 0) {
        double fwd = (log2(sd[0]) + (double)M + g_csum) * LN2_D;
        out[0] = (float)(fwd - g_gold);
    }
}

extern "C" void kernel_launch(void* const* d_in, const int* in_sizes, int n_in,
                              void* d_out, int out_size)
{
    const float* pred = nullptr;
    const int*   ref  = nullptr;
    const float* trans = nullptr;
    for (int i = 0; i < n_in; ++i) {
        if (in_sizes[i] == T_LEN)                 ref   = (const int*)d_in[i];
        else if (in_sizes[i] == L_LAB * L_LAB)    trans = (const float*)d_in[i];
        else if (in_sizes[i] == T_LEN * L_LAB)    pred  = (const float*)d_in[i];
    }
    crf_reset<<<8, 256>>>();
    crf_main<<<NBLK + 1, TPB>>>(pred, ref, trans);
    crf_final<<<1, TPB>>>(trans, (float*)d_out);
}

// round 10
// speedup vs baseline: 2.7774x; 2.7774x over previous
#include <cuda_runtime.h>
#include <cuda_fp16.h>
#include <cstdint>
#include <cstddef>

#define T_LEN 16384
#define L_LAB 1024
#define LOG2E 1.4426950408889634f
#define LN2_D 0.6931471805599453
#define CSIZE 16           // cluster size (16 SMs do all the work)
#define TPB   1024
#define ROWS_PER_BLK 64    // L_LAB / CSIZE

// ---- persistent scratch (no allocations allowed) ----
__device__ float  g_alpha[L_LAB];
__device__ double g_csum;
__device__ double g_gold;

static __device__ __forceinline__ float ex2f(float x) {
    float r; asm("ex2.approx.ftz.f32 %0, %1;" : "=f"(r) : "f"(x)); return r;
}
static __device__ __forceinline__ float lg2f_(float x) {
    float r; asm("lg2.approx.f32 %0, %1;" : "=f"(r) : "f"(x)); return r;
}
static __device__ __forceinline__ unsigned smem_u32(const void* p) {
    unsigned a;
    asm("{ .reg .u64 t; cvta.to.shared.u64 t, %1; cvt.u32.u64 %0, t; }"
        : "=r"(a) : "l"(p));
    return a;
}
// Store 8 bytes into the same smem offset of cluster CTA `peer`.
static __device__ __forceinline__ void st_dsmem64(unsigned localAddr, unsigned peer,
                                                  unsigned long long v) {
    unsigned r;
    asm volatile("mapa.shared::cluster.u32 %0, %1, %2;" : "=r"(r) : "r"(localAddr), "r"(peer));
    asm volatile("st.shared::cluster.b64 [%0], %1;" :: "r"(r), "l"(v) : "memory");
}
#define CLUSTER_SYNC() do { \
    asm volatile("barrier.cluster.arrive.aligned;" ::: "memory"); \
    asm volatile("barrier.cluster.wait.aligned;"   ::: "memory"); \
} while (0)

// Grid (16, 2), cluster (16,1,1):
//   y==0: the compute cluster (16 CTAs, 1024 threads each; one CTA per SM).
//   y==1, x==0: gold-path score; other y==1 blocks exit immediately (no cluster ops).
__global__ void __launch_bounds__(TPB, 1) __cluster_dims__(CSIZE, 1, 1)
crf_main(const float* __restrict__ pred,
         const int*   __restrict__ ref,
         const float* __restrict__ trans)
{
    if (blockIdx.y == 1) {
        if (blockIdx.x != 0) return;
        // ---- gold path score (separate cluster; never calls cluster.sync) ----
        __shared__ double red[TPB];
        int tid = threadIdx.x;
        double g = 0.0;
        for (int t = tid; t < T_LEN; t += TPB) {
            int r = __ldg(&ref[t]);
            int p = (t == 0) ? (L_LAB - 2) : __ldg(&ref[t - 1]);
            g += (double)__ldg(&pred[(size_t)t * L_LAB + r])
               + (double)__ldg(&trans[(size_t)r * L_LAB + p]);
        }
        red[tid] = g; __syncthreads();
        for (int s = TPB / 2; s > 0; s >>= 1) {
            if (tid < s) red[tid] += red[tid + s];
            __syncthreads();
        }
        if (tid == 0)
            g_gold = red[0] + (double)__ldg(&trans[(size_t)(L_LAB - 1) * L_LAB + __ldg(&ref[T_LEN - 1])]);
        return;
    }

    // ================= compute cluster =================
    __shared__ __align__(16) float sAlpha[2][L_LAB];  // exchanged alphas, parity-buffered
    __shared__ __align__(16) float sE[L_LAB];         // e[i] = 2^(alpha[i]-c)
    __shared__ __align__(8)  float sOut[ROWS_PER_BLK];

    const int tid = threadIdx.x;
    const int w = tid >> 5, l = tid & 31;
    const unsigned rank = blockIdx.x;            // cluster cta rank (cluster spans x)
    const int jA = (int)rank * ROWS_PER_BLK + 2 * w;   // this warp's rows: jA, jA+1

    // ---- precompute expW = 2^(W*log2e) = exp(W) for rows jA, jA+1 as packed fp16.
    // Element i = k*128 + 4*l + m. Pairs (m=0,1) and (m=2,3) per k.
    __half2 hA[16], hB[16];
    {
        const float* ta = trans + (size_t)jA * L_LAB;
        const float* tb = trans + (size_t)(jA + 1) * L_LAB;
        #pragma unroll
        for (int k = 0; k < 8; ++k) {
            float4 a4 = *reinterpret_cast<const float4*>(ta + k * 128 + 4 * l);
            float4 b4 = *reinterpret_cast<const float4*>(tb + k * 128 + 4 * l);
            hA[2 * k + 0] = __floats2half2_rn(ex2f(a4.x * LOG2E), ex2f(a4.y * LOG2E));
            hA[2 * k + 1] = __floats2half2_rn(ex2f(a4.z * LOG2E), ex2f(a4.w * LOG2E));
            hB[2 * k + 0] = __floats2half2_rn(ex2f(b4.x * LOG2E), ex2f(b4.y * LOG2E));
            hB[2 * k + 1] = __floats2half2_rn(ex2f(b4.z * LOG2E), ex2f(b4.w * LOG2E));
        }
    }

    // ---- step 1 closed form: alpha2(1)[j] = (W[j,START] + pred[0,j]) * log2e
    float2 fcur, fnext;           // feats for (this, next) step; meaningful on lane 0
    if (l == 0) {
        float wsA = __ldg(&trans[(size_t)jA * L_LAB + (L_LAB - 2)]);
        float wsB = __ldg(&trans[(size_t)(jA + 1) * L_LAB + (L_LAB - 2)]);
        float2 p0 = __ldg(reinterpret_cast<const float2*>(pred + jA));
        sOut[2 * w]     = (wsA + p0.x) * LOG2E;
        sOut[2 * w + 1] = (wsB + p0.y) * LOG2E;
        fcur = __ldg(reinterpret_cast<const float2*>(pred + (size_t)L_LAB + jA));
    }
    __syncthreads();
    if (w == 0) {                 // broadcast this block's 64-value chunk to all CTAs
        float2 f = *reinterpret_cast<float2*>(&sOut[2 * l]);
        unsigned long long v;
        asm("mov.b64 %0, {%1,%2};" : "=l"(v) : "f"(f.x), "f"(f.y));
        unsigned loc = smem_u32(&sAlpha[1][rank * ROWS_PER_BLK + 2 * l]);
        #pragma unroll
        for (unsigned p = 0; p < CSIZE; ++p) st_dsmem64(loc, p, v);
    }
    CLUSTER_SYNC();

    double csum = 0.0;

    // ---- main recurrence: iter t consumes alpha(t), produces alpha(t+1) ----
    for (int t = 1; t < T_LEN; ++t) {
        const int buf = t & 1, nbuf = buf ^ 1;

        // stage e[i] = 2^(alpha[i] - c); c = alpha[0] (deterministic normalizer)
        float c = sAlpha[buf][0];
        sE[tid] = ex2f(sAlpha[buf][tid] - c);
        if (rank == 0 && tid == 0) csum += (double)c;
        __syncthreads();

        if (l == 0 && t + 1 < T_LEN)     // prefetch next step's feats (lane 0)
            fnext = __ldg(reinterpret_cast<const float2*>(pred + (size_t)(t + 1) * L_LAB + jA));

        // SGEMV rows jA, jA+1: s = sum_i expW[j,i] * e[i]   (FMA pipe, no MUFU)
        float a0 = 0.f, a1 = 0.f, b0 = 0.f, b1 = 0.f;
        #pragma unroll
        for (int k = 0; k < 8; ++k) {
            float4 e4 = *reinterpret_cast<const float4*>(&sE[k * 128 + 4 * l]);
            float2 wa0 = __half22float2(hA[2 * k + 0]);
            float2 wa1 = __half22float2(hA[2 * k + 1]);
            float2 wb0 = __half22float2(hB[2 * k + 0]);
            float2 wb1 = __half22float2(hB[2 * k + 1]);
            a0 = fmaf(e4.x, wa0.x, a0); a1 = fmaf(e4.y, wa0.y, a1);
            a0 = fmaf(e4.z, wa1.x, a0); a1 = fmaf(e4.w, wa1.y, a1);
            b0 = fmaf(e4.x, wb0.x, b0); b1 = fmaf(e4.y, wb0.y, b1);
            b0 = fmaf(e4.z, wb1.x, b0); b1 = fmaf(e4.w, wb1.y, b1);
        }
        float sA = a0 + a1, sB = b0 + b1;
        #pragma unroll
        for (int o = 16; o > 0; o >>= 1) {
            sA += __shfl_xor_sync(0xffffffffu, sA, o);
            sB += __shfl_xor_sync(0xffffffffu, sB, o);
        }

        if (l == 0) {
            // stored alpha2(t+1) = lg2(s) + feat2   (c re-added via csum at the end)
            sOut[2 * w]     = lg2f_(sA) + fcur.x * LOG2E;
            sOut[2 * w + 1] = lg2f_(sB) + fcur.y * LOG2E;
            fcur = fnext;
        }
        __syncthreads();

        if (w == 0) {              // DSMEM broadcast of the new 64-value chunk
            float2 f = *reinterpret_cast<float2*>(&sOut[2 * l]);
            unsigned long long v;
            asm("mov.b64 %0, {%1,%2};" : "=l"(v) : "f"(f.x), "f"(f.y));
            unsigned loc = smem_u32(&sAlpha[nbuf][rank * ROWS_PER_BLK + 2 * l]);
            #pragma unroll
            for (unsigned p = 0; p < CSIZE; ++p) st_dsmem64(loc, p, v);
        }
        CLUSTER_SYNC();            // release/acquire: chunks visible; also block barrier
    }

    // alpha(T_LEN) sits in parity buffer (T_LEN & 1) == 0
    if (rank == 0) {
        g_alpha[tid] = sAlpha[0][tid];
        if (tid == 0) g_csum = csum;
    }
}

// Terminal: forward = LSE_j(alpha2(T)[j] + W2[STOP,j]) + csum, max-stabilized
// (the STOP row is uniformly -1e4; without the max everything underflows).
__global__ void crf_final(const float* __restrict__ trans, float* __restrict__ out)
{
    __shared__ float  sm[256];
    __shared__ double sd[256];
    int tid = threadIdx.x;

    float x[4];
    float m = -3.4e38f;
    #pragma unroll
    for (int q = 0; q < 4; ++q) {
        int jj = q * 256 + tid;
        float a  = g_alpha[jj];
        float wl = __ldg(&trans[(size_t)(L_LAB - 1) * L_LAB + jj]) * LOG2E;
        x[q] = a + wl;
        m = fmaxf(m, x[q]);
    }
    sm[tid] = m; __syncthreads();
    for (int s = 128; s > 0; s >>= 1) {
        if (tid < s) sm[tid] = fmaxf(sm[tid], sm[tid + s]);
        __syncthreads();
    }
    float M = sm[0];

    double loc = 0.0;
    #pragma unroll
    for (int q = 0; q < 4; ++q) loc += (double)ex2f(x[q] - M);
    sd[tid] = loc; __syncthreads();
    for (int s = 128; s > 0; s >>= 1) {
        if (tid < s) sd[tid] += sd[tid + s];
        __syncthreads();
    }
    if (tid == 0) {
        double fwd = (log2(sd[0]) + (double)M + g_csum) * LN2_D;
        out[0] = (float)(fwd - g_gold);
    }
}

extern "C" void kernel_launch(void* const* d_in, const int* in_sizes, int n_in,
                              void* d_out, int out_size)
{
    const float* pred = nullptr;
    const int*   ref  = nullptr;
    const float* trans = nullptr;
    for (int i = 0; i < n_in; ++i) {
        if (in_sizes[i] == T_LEN)                 ref   = (const int*)d_in[i];
        else if (in_sizes[i] == L_LAB * L_LAB)    trans = (const float*)d_in[i];
        else if (in_sizes[i] == T_LEN * L_LAB)    pred  = (const float*)d_in[i];
    }
    // cluster size 16 > portable limit 8: opt in (idempotent host-side call,
    // no stream work, safe under graph capture).
    cudaFuncSetAttribute(crf_main, cudaFuncAttributeNonPortableClusterSizeAllowed, 1);

    dim3 grid(CSIZE, 2);
    crf_main<<<grid, TPB>>>(pred, ref, trans);
    crf_final<<<1, 256>>>(trans, (float*)d_out);
}

// round 11
// speedup vs baseline: 3.1880x; 1.1478x over previous
#include <cuda_runtime.h>
#include <cuda_fp16.h>
#include <cstdint>
#include <cstddef>

#define T_LEN 16384
#define L_LAB 1024
#define LOG2E 1.4426950408889634f
#define LN2_D 0.6931471805599453
#define CSIZE 16           // cluster size (16 SMs do all the work)
#define TPB   1024
#define ROWS_PER_BLK 64    // L_LAB / CSIZE

// ---- persistent scratch (no allocations allowed) ----
__device__ float  g_alpha[L_LAB];
__device__ double g_csum;
__device__ double g_gold;

static __device__ __forceinline__ float ex2f(float x) {
    float r; asm("ex2.approx.ftz.f32 %0, %1;" : "=f"(r) : "f"(x)); return r;
}
static __device__ __forceinline__ float lg2f_(float x) {
    float r; asm("lg2.approx.f32 %0, %1;" : "=f"(r) : "f"(x)); return r;
}
static __device__ __forceinline__ unsigned smem_u32(const void* p) {
    unsigned a;
    asm("{ .reg .u64 t; cvta.to.shared.u64 t, %1; cvt.u32.u64 %0, t; }"
        : "=r"(a) : "l"(p));
    return a;
}
// Store 8 bytes into the same smem offset of cluster CTA `peer`.
static __device__ __forceinline__ void st_dsmem64(unsigned localAddr, unsigned peer,
                                                  unsigned long long v) {
    unsigned r;
    asm volatile("mapa.shared::cluster.u32 %0, %1, %2;" : "=r"(r) : "r"(localAddr), "r"(peer));
    asm volatile("st.shared::cluster.b64 [%0], %1;" :: "r"(r), "l"(v) : "memory");
}
#define CLUSTER_SYNC() do { \
    asm volatile("barrier.cluster.arrive.aligned;" ::: "memory"); \
    asm volatile("barrier.cluster.wait.aligned;"   ::: "memory"); \
} while (0)

// Grid (16, 2), cluster (16,1,1):
//   y==0: the compute cluster (one CTA per SM, 1024 threads).
//   y==1, x==0: gold-path score; other y==1 blocks exit (their cluster never syncs).
__global__ void __launch_bounds__(TPB, 1) __cluster_dims__(CSIZE, 1, 1)
crf_main(const float* __restrict__ pred,
         const int*   __restrict__ ref,
         const float* __restrict__ trans)
{
    if (blockIdx.y == 1) {
        if (blockIdx.x != 0) return;
        __shared__ double red[TPB];
        int tid = threadIdx.x;
        double g = 0.0;
        for (int t = tid; t < T_LEN; t += TPB) {
            int r = __ldg(&ref[t]);
            int p = (t == 0) ? (L_LAB - 2) : __ldg(&ref[t - 1]);
            g += (double)__ldg(&pred[(size_t)t * L_LAB + r])
               + (double)__ldg(&trans[(size_t)r * L_LAB + p]);
        }
        red[tid] = g; __syncthreads();
        for (int s = TPB / 2; s > 0; s >>= 1) {
            if (tid < s) red[tid] += red[tid + s];
            __syncthreads();
        }
        if (tid == 0)
            g_gold = red[0] + (double)__ldg(&trans[(size_t)(L_LAB - 1) * L_LAB + __ldg(&ref[T_LEN - 1])]);
        return;
    }

    // ================= compute cluster =================
    __shared__ __align__(16) float  sAlpha[2][L_LAB];  // exchanged alphas (parity)
    __shared__ __align__(16) __half sEh[L_LAB];        // e[i] = 2^(alpha[i]-m), fp16
    __shared__ __align__(8)  float  sOut[ROWS_PER_BLK];
    __shared__ float sRed[40];                         // warp maxima + broadcast slot

    const int tid = threadIdx.x;
    const int w = tid >> 5, l = tid & 31;
    const unsigned rank = blockIdx.x;
    const int jA = (int)rank * ROWS_PER_BLK + 2 * w;   // warp's rows: jA, jA+1

    // ---- precompute expW = exp(W) for rows jA, jA+1, packed fp16.
    // Thread (w,l), chunk k2=0..3 covers labels i = k2*256 + 8l + m, m=0..7.
    __half2 hA[16], hB[16];
    {
        const float* ta = trans + (size_t)jA * L_LAB;
        const float* tb = ta + L_LAB;
        #pragma unroll
        for (int k2 = 0; k2 < 4; ++k2) {
            float4 u = *reinterpret_cast<const float4*>(ta + k2 * 256 + 8 * l);
            float4 v = *reinterpret_cast<const float4*>(ta + k2 * 256 + 8 * l + 4);
            hA[k2 * 4 + 0] = __floats2half2_rn(ex2f(u.x * LOG2E), ex2f(u.y * LOG2E));
            hA[k2 * 4 + 1] = __floats2half2_rn(ex2f(u.z * LOG2E), ex2f(u.w * LOG2E));
            hA[k2 * 4 + 2] = __floats2half2_rn(ex2f(v.x * LOG2E), ex2f(v.y * LOG2E));
            hA[k2 * 4 + 3] = __floats2half2_rn(ex2f(v.z * LOG2E), ex2f(v.w * LOG2E));
            u = *reinterpret_cast<const float4*>(tb + k2 * 256 + 8 * l);
            v = *reinterpret_cast<const float4*>(tb + k2 * 256 + 8 * l + 4);
            hB[k2 * 4 + 0] = __floats2half2_rn(ex2f(u.x * LOG2E), ex2f(u.y * LOG2E));
            hB[k2 * 4 + 1] = __floats2half2_rn(ex2f(u.z * LOG2E), ex2f(u.w * LOG2E));
            hB[k2 * 4 + 2] = __floats2half2_rn(ex2f(v.x * LOG2E), ex2f(v.y * LOG2E));
            hB[k2 * 4 + 3] = __floats2half2_rn(ex2f(v.z * LOG2E), ex2f(v.w * LOG2E));
        }
    }

    // ---- step 1 closed form: alpha2(1)[j] = (W[j,START] + pred[0,j]) * log2e
    float2 fcur, fnext;               // feats (lane 0 only)
    if (l == 0) {
        float wsA = __ldg(&trans[(size_t)jA * L_LAB + (L_LAB - 2)]);
        float wsB = __ldg(&trans[(size_t)(jA + 1) * L_LAB + (L_LAB - 2)]);
        float2 p0 = __ldg(reinterpret_cast<const float2*>(pred + jA));
        sOut[2 * w]     = (wsA + p0.x) * LOG2E;
        sOut[2 * w + 1] = (wsB + p0.y) * LOG2E;
        fcur = __ldg(reinterpret_cast<const float2*>(pred + (size_t)L_LAB + jA));
    }
    __syncthreads();
    if (w < CSIZE) {                  // warp p pushes this block's chunk to peer p
        float2 f = *reinterpret_cast<float2*>(&sOut[2 * l]);
        unsigned long long v;
        asm("mov.b64 %0, {%1,%2};" : "=l"(v) : "f"(f.x), "f"(f.y));
        st_dsmem64(smem_u32(&sAlpha[1][rank * ROWS_PER_BLK + 2 * l]), (unsigned)w, v);
    }
    CLUSTER_SYNC();

    double csum = 0.0;

    for (int t = 1; t < T_LEN; ++t) {
        const int buf = t & 1, nbuf = buf ^ 1;

        // ---- deterministic block max m over the full (replicated) alpha vector.
        // Identical data + identical reduction order on every CTA -> identical m.
        float a = sAlpha[buf][tid];
        float mx = a;
        #pragma unroll
        for (int o = 16; o > 0; o >>= 1) mx = fmaxf(mx, __shfl_xor_sync(0xffffffffu, mx, o));
        if (l == 0) sRed[w] = mx;
        __syncthreads();
        if (tid < 32) {
            float mm = sRed[tid];
            #pragma unroll
            for (int o = 16; o > 0; o >>= 1) mm = fmaxf(mm, __shfl_xor_sync(0xffffffffu, mm, o));
            if (tid == 0) sRed[33] = mm;
        }
        __syncthreads();
        const float m = sRed[33];

        // e[i] = 2^(alpha[i]-m) <= 1  -> fp16 accumulation cannot overflow
        sEh[tid] = __float2half_rn(ex2f(a - m));
        if (rank == 0 && tid == 0) csum += (double)m;
        __syncthreads();

        if (l == 0 && t + 1 < T_LEN)
            fnext = __ldg(reinterpret_cast<const float2*>(pred + (size_t)(t + 1) * L_LAB + jA));

        // ---- rows jA, jA+1: s = sum_i expW[j,i]*e[i], packed half2 HFMA2 ----
        __half2 pA[4], pB[4];
        #pragma unroll
        for (int k2 = 0; k2 < 4; ++k2) {
            uint4 raw = *reinterpret_cast<const uint4*>(&sEh[k2 * 256 + 8 * l]);
            __half2 e0 = *reinterpret_cast<__half2*>(&raw.x);
            __half2 e1 = *reinterpret_cast<__half2*>(&raw.y);
            __half2 e2 = *reinterpret_cast<__half2*>(&raw.z);
            __half2 e3 = *reinterpret_cast<__half2*>(&raw.w);
            __half2 aa = __hmul2(e0, hA[k2 * 4 + 0]);
            aa = __hfma2(e1, hA[k2 * 4 + 1], aa);
            aa = __hfma2(e2, hA[k2 * 4 + 2], aa);
            aa = __hfma2(e3, hA[k2 * 4 + 3], aa);
            pA[k2] = aa;
            __half2 bb = __hmul2(e0, hB[k2 * 4 + 0]);
            bb = __hfma2(e1, hB[k2 * 4 + 1], bb);
            bb = __hfma2(e2, hB[k2 * 4 + 2], bb);
            bb = __hfma2(e3, hB[k2 * 4 + 3], bb);
            pB[k2] = bb;
        }
        // 32-term partials (<= ~4.3e3, safe in fp16); then to f32 for lane reduce
        __half2 hsA = __hadd2(__hadd2(pA[0], pA[1]), __hadd2(pA[2], pA[3]));
        __half2 hsB = __hadd2(__hadd2(pB[0], pB[1]), __hadd2(pB[2], pB[3]));
        float2 fa = __half22float2(hsA);
        float2 fb = __half22float2(hsB);
        float sA = fa.x + fa.y, sB = fb.x + fb.y;
        #pragma unroll
        for (int o = 16; o > 0; o >>= 1) {
            sA += __shfl_xor_sync(0xffffffffu, sA, o);
            sB += __shfl_xor_sync(0xffffffffu, sB, o);
        }

        if (l == 0) {
            sOut[2 * w]     = lg2f_(sA) + fcur.x * LOG2E;
            sOut[2 * w + 1] = lg2f_(sB) + fcur.y * LOG2E;
            fcur = fnext;
        }
        __syncthreads();

        if (w < CSIZE) {              // parallel DSMEM broadcast: warp p -> peer p
            float2 f = *reinterpret_cast<float2*>(&sOut[2 * l]);
            unsigned long long v;
            asm("mov.b64 %0, {%1,%2};" : "=l"(v) : "f"(f.x), "f"(f.y));
            st_dsmem64(smem_u32(&sAlpha[nbuf][rank * ROWS_PER_BLK + 2 * l]), (unsigned)w, v);
        }
        CLUSTER_SYNC();               // orders DSMEM stores; doubles as block barrier
    }

    // alpha(T_LEN) sits in parity buffer (T_LEN & 1) == 0
    if (rank == 0) {
        g_alpha[tid] = sAlpha[0][tid];
        if (tid == 0) g_csum = csum;
    }
}

// Terminal: forward = LSE_j(alpha2(T)[j] + W2[STOP,j]) + csum, max-stabilized
// (the STOP row is uniformly -1e4; without the max everything underflows).
__global__ void crf_final(const float* __restrict__ trans, float* __restrict__ out)
{
    __shared__ float  sm[256];
    __shared__ double sd[256];
    int tid = threadIdx.x;

    float x[4];
    float m = -3.4e38f;
    #pragma unroll
    for (int q = 0; q < 4; ++q) {
        int jj = q * 256 + tid;
        float a  = g_alpha[jj];
        float wl = __ldg(&trans[(size_t)(L_LAB - 1) * L_LAB + jj]) * LOG2E;
        x[q] = a + wl;
        m = fmaxf(m, x[q]);
    }
    sm[tid] = m; __syncthreads();
    for (int s = 128; s > 0; s >>= 1) {
        if (tid < s) sm[tid] = fmaxf(sm[tid], sm[tid + s]);
        __syncthreads();
    }
    float M = sm[0];

    double loc = 0.0;
    #pragma unroll
    for (int q = 0; q < 4; ++q) loc += (double)ex2f(x[q] - M);
    sd[tid] = loc; __syncthreads();
    for (int s = 128; s > 0; s >>= 1) {
        if (tid < s) sd[tid] += sd[tid + s];
        __syncthreads();
    }
    if (tid == 0) {
        double fwd = (log2(sd[0]) + (double)M + g_csum) * LN2_D;
        out[0] = (float)(fwd - g_gold);
    }
}

extern "C" void kernel_launch(void* const* d_in, const int* in_sizes, int n_in,
                              void* d_out, int out_size)
{
    const float* pred = nullptr;
    const int*   ref  = nullptr;
    const float* trans = nullptr;
    for (int i = 0; i < n_in; ++i) {
        if (in_sizes[i] == T_LEN)                 ref   = (const int*)d_in[i];
        else if (in_sizes[i] == L_LAB * L_LAB)    trans = (const float*)d_in[i];
        else if (in_sizes[i] == T_LEN * L_LAB)    pred  = (const float*)d_in[i];
    }
    cudaFuncSetAttribute(crf_main, cudaFuncAttributeNonPortableClusterSizeAllowed, 1);

    dim3 grid(CSIZE, 2);
    crf_main<<<grid, TPB>>>(pred, ref, trans);
    crf_final<<<1, 256>>>(trans, (float*)d_out);
}